// round 15
// baseline (speedup 1.0000x reference)
#include <cuda_runtime.h>
#include <math.h>

#define QN    4096
#define SRCN  32768
#define CC    128
#define KNN   32
#define EDGES (2*QN*KNN)   /* 262144 */
#define MHID  384

// ---------------- device scratch (static, allocation-free) ----------------
__device__ float g_v[2][SRCN*CC];       // src_feat @ Wv[l]
__device__ float g_qproj[QN*CC];
__device__ float g_Pq[2][QN*64];        // ctx @ Wr1[l][32:] + br1[l]
__device__ float g_svw[2][EDGES];
__device__ unsigned char g_mask[EDGES];
__device__ float g_agg[QN*CC];
__device__ float g_obuf[QN*CC];
__device__ float g_hbuf[QN*MHID];
__device__ float g_feat[QN*CC];
__device__ float g_wof1[2][CC*MHID];    // Wo[l] @ Wf1[l]
__device__ float g_bcomb[2*MHID];       // bo[l]@Wf1[l] + bf1[l]
__device__ float g_Ff1[QN*MHID];        // feat@Wf1 + bcomb (per current layer)

// saturating tanh-gelu: t = 1 - 2/(exp(2y)+1) == tanh(y), inf-safe
__device__ __forceinline__ float gelu_fast(float x) {
    float u = 1.5957691216057308f * (x + 0.044715f*x*x*x);
    float e = __expf(u);
    float t = 1.0f - 2.0f/(e + 1.0f);
    return 0.5f*x*(1.0f + t);
}

// ============ big-tile SGEMM: 128x128 block, 8x8/thread, double-buffered ==
// act: 0 = none, 1 = gelu(bias+x), 2 = gelu(x + resid)  [resid-before-act]
__global__ __launch_bounds__(256) void gemm128(
    const float* __restrict__ A, const float* __restrict__ B0, float* __restrict__ C0,
    int M, int N, int K,
    const float* __restrict__ bias, const float* __restrict__ resid, int act,
    long long strideB, long long strideC)
{
    const float* B = B0 + (long long)blockIdx.z * strideB;
    float*       C = C0 + (long long)blockIdx.z * strideC;
    __shared__ float As[2][8][128];
    __shared__ float Bs[2][8][128];
    int tid  = threadIdx.x;
    int m0   = blockIdx.y * 128, n0 = blockIdx.x * 128;
    int arow = tid >> 1,  acol = (tid & 1) * 4;
    int brow = tid >> 5,  bcol = (tid & 31) * 4;
    int tx   = tid & 15,  ty   = tid >> 4;
    float acc[8][8] = {};

    const float* Aptr = A + (size_t)(m0 + arow) * K + acol;
    const float* Bptr = B + (size_t)brow * N + n0 + bcol;

    float4 av = *(const float4*)Aptr;
    float4 bv = *(const float4*)Bptr;
    As[0][acol+0][arow] = av.x; As[0][acol+1][arow] = av.y;
    As[0][acol+2][arow] = av.z; As[0][acol+3][arow] = av.w;
    *(float4*)&Bs[0][brow][bcol] = bv;
    __syncthreads();

    int buf = 0;
    for (int kk = 8; kk < K; kk += 8) {
        av = *(const float4*)(Aptr + kk);
        bv = *(const float4*)(Bptr + (size_t)kk * N);
        #pragma unroll
        for (int k = 0; k < 8; k++) {
            float a[8], b[8];
            *(float4*)&a[0] = *(float4*)&As[buf][k][ty*4];
            *(float4*)&a[4] = *(float4*)&As[buf][k][64 + ty*4];
            *(float4*)&b[0] = *(float4*)&Bs[buf][k][tx*4];
            *(float4*)&b[4] = *(float4*)&Bs[buf][k][64 + tx*4];
            #pragma unroll
            for (int i = 0; i < 8; i++)
                #pragma unroll
                for (int j = 0; j < 8; j++)
                    acc[i][j] = fmaf(a[i], b[j], acc[i][j]);
        }
        buf ^= 1;
        As[buf][acol+0][arow] = av.x; As[buf][acol+1][arow] = av.y;
        As[buf][acol+2][arow] = av.z; As[buf][acol+3][arow] = av.w;
        *(float4*)&Bs[buf][brow][bcol] = bv;
        __syncthreads();
    }
    #pragma unroll
    for (int k = 0; k < 8; k++) {
        float a[8], b[8];
        *(float4*)&a[0] = *(float4*)&As[buf][k][ty*4];
        *(float4*)&a[4] = *(float4*)&As[buf][k][64 + ty*4];
        *(float4*)&b[0] = *(float4*)&Bs[buf][k][tx*4];
        *(float4*)&b[4] = *(float4*)&Bs[buf][k][64 + tx*4];
        #pragma unroll
        for (int i = 0; i < 8; i++)
            #pragma unroll
            for (int j = 0; j < 8; j++)
                acc[i][j] = fmaf(a[i], b[j], acc[i][j]);
    }

    #pragma unroll
    for (int i = 0; i < 8; i++) {
        int row = m0 + ((i < 4) ? (ty*4 + i) : (64 + ty*4 + i - 4));
        #pragma unroll
        for (int j = 0; j < 8; j++) {
            int col = n0 + ((j < 4) ? (tx*4 + j) : (64 + tx*4 + j - 4));
            float x = acc[i][j];
            if (bias)  x += bias[col];
            if (act == 2) {
                x = gelu_fast(x + resid[(size_t)row*N + col]);
            } else {
                if (act == 1) x = gelu_fast(x);
                if (resid)    x += resid[(size_t)row*N + col];
            }
            C[(size_t)row*N + col] = x;
        }
    }
}

// ============ 64x64 SGEMM (z-batched) ====================================
__global__ __launch_bounds__(256) void gemm64(
    const float* __restrict__ A, const float* __restrict__ B0, float* __restrict__ C0,
    int M, int N, int K,
    const float* __restrict__ bias0, const float* __restrict__ resid, int act,
    long long strideB, long long strideC, long long strideBias)
{
    const float* B = B0 + (long long)blockIdx.z * strideB;
    float*       C = C0 + (long long)blockIdx.z * strideC;
    const float* bias = bias0 ? (bias0 + (long long)blockIdx.z * strideBias) : nullptr;
    __shared__ float As[16][64];
    __shared__ float Bs[16][64];
    int tid = threadIdx.x;
    int m0 = blockIdx.y * 64, n0 = blockIdx.x * 64;
    int arow = tid >> 2, acol = (tid & 3) * 4;
    int brow = tid >> 4, bcol = (tid & 15) * 4;
    int tx = tid & 15, ty = tid >> 4;
    float acc[4][4] = {};

    for (int kk = 0; kk < K; kk += 16) {
        float4 av = *(const float4*)&A[(size_t)(m0 + arow)*K + kk + acol];
        float4 bv = *(const float4*)&B[(size_t)(kk + brow)*N + n0 + bcol];
        As[acol+0][arow] = av.x; As[acol+1][arow] = av.y;
        As[acol+2][arow] = av.z; As[acol+3][arow] = av.w;
        *(float4*)&Bs[brow][bcol] = bv;
        __syncthreads();
        #pragma unroll
        for (int k = 0; k < 16; k++) {
            float4 a4 = *(float4*)&As[k][ty*4];
            float4 b4 = *(float4*)&Bs[k][tx*4];
            acc[0][0] = fmaf(a4.x, b4.x, acc[0][0]); acc[0][1] = fmaf(a4.x, b4.y, acc[0][1]);
            acc[0][2] = fmaf(a4.x, b4.z, acc[0][2]); acc[0][3] = fmaf(a4.x, b4.w, acc[0][3]);
            acc[1][0] = fmaf(a4.y, b4.x, acc[1][0]); acc[1][1] = fmaf(a4.y, b4.y, acc[1][1]);
            acc[1][2] = fmaf(a4.y, b4.z, acc[1][2]); acc[1][3] = fmaf(a4.y, b4.w, acc[1][3]);
            acc[2][0] = fmaf(a4.z, b4.x, acc[2][0]); acc[2][1] = fmaf(a4.z, b4.y, acc[2][1]);
            acc[2][2] = fmaf(a4.z, b4.z, acc[2][2]); acc[2][3] = fmaf(a4.z, b4.w, acc[2][3]);
            acc[3][0] = fmaf(a4.w, b4.x, acc[3][0]); acc[3][1] = fmaf(a4.w, b4.y, acc[3][1]);
            acc[3][2] = fmaf(a4.w, b4.z, acc[3][2]); acc[3][3] = fmaf(a4.w, b4.w, acc[3][3]);
        }
        __syncthreads();
    }
    #pragma unroll
    for (int i = 0; i < 4; i++) {
        int row = m0 + ty*4 + i;
        #pragma unroll
        for (int j = 0; j < 4; j++) {
            int col = n0 + tx*4 + j;
            float x = acc[i][j];
            if (bias)  x += bias[col];
            if (act == 2) {
                x = gelu_fast(x + resid[(size_t)row*N + col]);
            } else {
                if (act == 1) x = gelu_fast(x);
                if (resid)    x += resid[(size_t)row*N + col];
            }
            C[(size_t)row*N + col] = x;
        }
    }
}

// ---------------- bcomb[l][j] = bf1[l][j] + sum_c bo[l][c]*Wf1[l][c][j] ---
__global__ void bcomb_kernel(const float* __restrict__ Wf1,
                             const float* __restrict__ bo,
                             const float* __restrict__ bf1,
                             float* __restrict__ out)
{
    int idx = blockIdx.x*blockDim.x + threadIdx.x;
    if (idx >= 2*MHID) return;
    int l = idx / MHID, j = idx % MHID;
    float s = bf1[l*MHID + j];
    const float* w = Wf1 + (size_t)l*CC*MHID + j;
    const float* b = bo + l*CC;
    for (int c = 0; c < CC; c++) s = fmaf(b[c], w[(size_t)c*MHID], s);
    out[idx] = s;
}

// ======== tiled svw: 64 edges/block (1 tile), both layers, smem GEMM =====
__global__ __launch_bounds__(256) void svw_tile_kernel(
    const float* __restrict__ qpos, const float* __restrict__ spos,
    const int* __restrict__ esrc, const int* __restrict__ edst,
    const int* __restrict__ escale,
    const float* __restrict__ Wr1, const float* __restrict__ Wr2,
    const float* __restrict__ br2,
    const float* __restrict__ Pq /* [2][QN*64] */,
    float* __restrict__ svw /* [2][EDGES] */)
{
    __shared__ float Ws[2][32][64];
    __shared__ float W2s[2][64][9];
    __shared__ float b2s[2][9];
    __shared__ float bess_s[64][33];
    __shared__ float sh_s[64][9];
    __shared__ float Pq_s[2][2][64];
    __shared__ float s1_s[64], c1_s[64], norm_s[64];
    __shared__ int   dst_s[2];
    __shared__ float red[16][66];

    int tid = threadIdx.x;
    int e0g = blockIdx.x * 64;

    for (int i = tid; i < 2*32*64; i += 256) {
        int l = i >> 11, rem = i & 2047;
        Ws[l][rem >> 6][rem & 63] = Wr1[l*96*64 + rem];
    }
    for (int i = tid; i < 2*64*9; i += 256) {
        int l = i / 576, rem = i % 576;
        W2s[l][rem / 9][rem % 9] = Wr2[l*64*9 + rem];
    }
    if (tid < 18) b2s[tid/9][tid%9] = br2[tid];

    if (tid < 64) {
        int eg = e0g + tid;
        int s = esrc[eg], d = edst[eg], sc = escale[eg];
        float cut = sc ? 0.2f : 0.1f;
        float dx = qpos[d*3+0] - spos[s*3+0];
        float dy = qpos[d*3+1] - spos[s*3+1];
        float dz = qpos[d*3+2] - spos[s*3+2];
        float d2 = __fadd_rn(__fadd_rn(__fmul_rn(dx,dx), __fmul_rn(dy,dy)), __fmul_rn(dz,dz));
        g_mask[eg] = (d2 < __fmul_rn(cut,cut)) ? 1 : 0;
        float r = sqrtf(d2 + 1e-12f), ir = 1.0f/r;
        float ux = dx*ir, uy = dy*ir, uz = dz*ir;
        sh_s[tid][0] = 1.0f;  sh_s[tid][1] = ux;  sh_s[tid][2] = uy;  sh_s[tid][3] = uz;
        sh_s[tid][4] = ux*uy; sh_s[tid][5] = uy*uz;
        sh_s[tid][6] = uz*uz - (1.0f/3.0f);
        sh_s[tid][7] = ux*uz; sh_s[tid][8] = ux*ux - uy*uy;
        float x = 3.14159265358979f * r / cut;
        float s1, c1; sincosf(x, &s1, &c1);
        s1_s[tid] = s1; c1_s[tid] = c1;
        norm_s[tid] = sqrtf(2.0f/cut) * ir;
        if (tid == 0)  dst_s[0] = d;
        if (tid == 32) dst_s[1] = d;
    }
    __syncthreads();

    {
        int l = tid >> 7, ql = (tid >> 6) & 1, h = tid & 63;
        Pq_s[l][ql][h] = Pq[(size_t)l*QN*64 + dst_s[ql]*64 + h];
    }
    {
        int e = tid & 63, kg = tid >> 6;
        float s1 = s1_s[e], c1 = c1_s[e], nrm = norm_s[e];
        float C = c1, S = s1;
        if (kg) {
            float c2 = c1*c1 - s1*s1, s2 = 2.0f*c1*s1;
            float c4 = c2*c2 - s2*s2, s4 = 2.0f*c2*s2;
            float c8 = c4*c4 - s4*s4, s8 = 2.0f*c4*s4;
            for (int q = 0; q < kg; q++) {
                float nc = C*c8 - S*s8, ns = S*c8 + C*s8;
                C = nc; S = ns;
            }
        }
        #pragma unroll
        for (int u = 0; u < 8; u++) {
            bess_s[e][kg*8 + u] = S * nrm;
            float nc = C*c1 - S*s1, ns = S*c1 + C*s1;
            C = nc; S = ns;
        }
    }
    __syncthreads();

    int te = tid & 15, th = tid >> 4;
    #pragma unroll
    for (int l = 0; l < 2; l++) {
        float acc[4][4];
        #pragma unroll
        for (int j = 0; j < 4; j++) {
            int e = te + 16*j, ql = e >> 5;
            #pragma unroll
            for (int hh = 0; hh < 4; hh++)
                acc[j][hh] = Pq_s[l][ql][th*4 + hh];
        }
        #pragma unroll 8
        for (int k = 0; k < 32; k++) {
            float4 w = *(const float4*)&Ws[l][k][th*4];
            #pragma unroll
            for (int j = 0; j < 4; j++) {
                float b = bess_s[te + 16*j][k];
                acc[j][0] = fmaf(b, w.x, acc[j][0]);
                acc[j][1] = fmaf(b, w.y, acc[j][1]);
                acc[j][2] = fmaf(b, w.z, acc[j][2]);
                acc[j][3] = fmaf(b, w.w, acc[j][3]);
            }
        }
        #pragma unroll
        for (int j = 0; j < 4; j++)
            #pragma unroll
            for (int hh = 0; hh < 4; hh++)
                acc[j][hh] = gelu_fast(acc[j][hh]);

        float w2r[4][9];
        #pragma unroll
        for (int hh = 0; hh < 4; hh++)
            #pragma unroll
            for (int i = 0; i < 9; i++)
                w2r[hh][i] = W2s[l][th*4 + hh][i];

        #pragma unroll
        for (int j = 0; j < 4; j++) {
            int e = te + 16*j;
            float shl[9];
            #pragma unroll
            for (int i = 0; i < 9; i++) shl[i] = sh_s[e][i];
            float p = 0.f;
            #pragma unroll
            for (int hh = 0; hh < 4; hh++) {
                float t2 = 0.f;
                #pragma unroll
                for (int i = 0; i < 9; i++) t2 = fmaf(w2r[hh][i], shl[i], t2);
                p = fmaf(acc[j][hh], t2, p);
            }
            red[th][e] = p;
        }
        __syncthreads();
        if (tid < 64) {
            float s = 0.f;
            #pragma unroll
            for (int u = 0; u < 16; u++) s += red[u][tid];
            float sb = 0.f;
            #pragma unroll
            for (int i = 0; i < 9; i++) sb = fmaf(b2s[l][i], sh_s[tid][i], sb);
            svw[(size_t)l*EDGES + e0g + tid] = s + sb;
        }
        __syncthreads();
    }
}

// ---------------- per-query attention: skip-rescale online softmax -------
__global__ __launch_bounds__(256) void attn_kernel(const int* __restrict__ esrc, int layer)
{
    int lane = threadIdx.x & 31;
    int q = (blockIdx.x * blockDim.x + threadIdx.x) >> 5;
    if (q >= QN) return;
    const float* vbuf = g_v[layer];
    const float* svw  = g_svw[layer];

    float4 qv = *(const float4*)&g_qproj[q*CC + lane*4];
    float m[4], d[4], acc[4][4];
    #pragma unroll
    for (int u = 0; u < 4; u++) {
        m[u] = -1e30f; d[u] = 0.f;
        acc[u][0]=acc[u][1]=acc[u][2]=acc[u][3]=0.f;
    }

    #pragma unroll
    for (int half = 0; half < 2; half++) {
        int base = q*KNN + half*QN*KNN;
        #pragma unroll
        for (int jj = 0; jj < 8; jj++) {
            #pragma unroll
            for (int u = 0; u < 4; u++) {
                int e = base + jj*4 + u;
                int src = esrc[e];
                float w  = svw[e];
                float mf = (float)g_mask[e];
                float4 v4 = *(const float4*)&vbuf[(size_t)src*CC + lane*4];
                float p = qv.x*v4.x + qv.y*v4.y + qv.z*v4.z + qv.w*v4.w;
                p += __shfl_xor_sync(0xffffffffu, p, 1);
                p += __shfl_xor_sync(0xffffffffu, p, 2);
                p += __shfl_xor_sync(0xffffffffu, p, 4);
                float z = p * w * 0.17677669529663687f;
                float lk = (z > 0.f) ? z : 0.2f*z;
                float logit = (mf > 0.f) ? lk : -1e30f;
                if (logit > m[u]) {
                    float scl = __expf(m[u] - logit);
                    d[u]      *= scl;
                    acc[u][0] *= scl; acc[u][1] *= scl;
                    acc[u][2] *= scl; acc[u][3] *= scl;
                    m[u] = logit;
                }
                float el = __expf(logit - m[u]) * mf;
                d[u] += el;
                float ew = el * w;
                acc[u][0] = fmaf(ew, v4.x, acc[u][0]);
                acc[u][1] = fmaf(ew, v4.y, acc[u][1]);
                acc[u][2] = fmaf(ew, v4.z, acc[u][2]);
                acc[u][3] = fmaf(ew, v4.w, acc[u][3]);
            }
        }
    }
    float M = fmaxf(fmaxf(m[0], m[1]), fmaxf(m[2], m[3]));
    float D = 0.f, A0 = 0.f, A1 = 0.f, A2 = 0.f, A3 = 0.f;
    #pragma unroll
    for (int u = 0; u < 4; u++) {
        float s = __expf(m[u] - M);
        D  += d[u]*s;
        A0 = fmaf(acc[u][0], s, A0);
        A1 = fmaf(acc[u][1], s, A1);
        A2 = fmaf(acc[u][2], s, A2);
        A3 = fmaf(acc[u][3], s, A3);
    }
    float inv = 1.0f / (D + 1e-12f);
    *(float4*)&g_agg[q*CC + lane*4] = make_float4(A0*inv, A1*inv, A2*inv, A3*inv);
}

// ---------------- host orchestration -------------------------------------
// Algebraic restructure: h = gelu(agg@(Wo@Wf1) + [feat@Wf1 + bo@Wf1 + bf1]).
// Ff1 moves off the critical path; out and h run concurrently after attn.
extern "C" void kernel_launch(void* const* d_in, const int* in_sizes, int n_in,
                              void* d_out, int out_size)
{
    const float* qpos  = (const float*)d_in[0];
    const float* qfeat = (const float*)d_in[1];
    const float* spos  = (const float*)d_in[2];
    const float* sfeat = (const float*)d_in[3];
    const float* ctx   = (const float*)d_in[4];
    const float* Wq    = (const float*)d_in[5];
    const float* Wv    = (const float*)d_in[6];
    const float* Wo    = (const float*)d_in[7];
    const float* bo    = (const float*)d_in[8];
    const float* Wr1   = (const float*)d_in[9];
    const float* br1   = (const float*)d_in[10];
    const float* Wr2   = (const float*)d_in[11];
    const float* br2   = (const float*)d_in[12];
    const float* Wf1   = (const float*)d_in[13];
    const float* bf1   = (const float*)d_in[14];
    const float* Wf2   = (const float*)d_in[15];
    const float* bf2   = (const float*)d_in[16];
    const int*   esrc  = (const int*)d_in[17];
    const int*   edst  = (const int*)d_in[18];
    const int*   escal = (const int*)d_in[19];
    (void)in_sizes; (void)n_in; (void)out_size;

    float *v_p, *qproj_p, *Pq_p, *agg_p, *obuf_p, *hbuf_p, *feat_p, *svw_p;
    float *wof1_p, *bcomb_p, *Ff1_p;
    cudaGetSymbolAddress((void**)&v_p,     g_v);
    cudaGetSymbolAddress((void**)&qproj_p, g_qproj);
    cudaGetSymbolAddress((void**)&Pq_p,    g_Pq);
    cudaGetSymbolAddress((void**)&agg_p,   g_agg);
    cudaGetSymbolAddress((void**)&obuf_p,  g_obuf);
    cudaGetSymbolAddress((void**)&hbuf_p,  g_hbuf);
    cudaGetSymbolAddress((void**)&feat_p,  g_feat);
    cudaGetSymbolAddress((void**)&svw_p,   g_svw);
    cudaGetSymbolAddress((void**)&wof1_p,  g_wof1);
    cudaGetSymbolAddress((void**)&bcomb_p, g_bcomb);
    cudaGetSymbolAddress((void**)&Ff1_p,   g_Ff1);

    static cudaStream_t sB = nullptr;
    static cudaEvent_t evFork=nullptr, evJoin=nullptr, evAgg0=nullptr,
                       evH0=nullptr, evFeat=nullptr, evAgg1=nullptr, evH1=nullptr;
    if (sB == nullptr) {
        cudaStreamCreateWithFlags(&sB, cudaStreamNonBlocking);
        cudaEventCreateWithFlags(&evFork, cudaEventDisableTiming);
        cudaEventCreateWithFlags(&evJoin, cudaEventDisableTiming);
        cudaEventCreateWithFlags(&evAgg0, cudaEventDisableTiming);
        cudaEventCreateWithFlags(&evH0,   cudaEventDisableTiming);
        cudaEventCreateWithFlags(&evFeat, cudaEventDisableTiming);
        cudaEventCreateWithFlags(&evAgg1, cudaEventDisableTiming);
        cudaEventCreateWithFlags(&evH1,   cudaEventDisableTiming);
    }

    dim3 thr(256);

    // ---- fork ----
    cudaEventRecord(evFork, 0);
    cudaStreamWaitEvent(sB, evFork, 0);

    // side stream: Pq l0, Pq l1 -> svw (edge pipeline)
    for (int l = 0; l < 2; l++)
        gemm64<<<dim3(1, QN/64, 1), thr, 0, sB>>>(
            ctx, Wr1 + l*96*64 + 32*64, Pq_p + (size_t)l*QN*64, QN, 64, 64,
            br1 + l*64, nullptr, 0, 0LL, 0LL, 0LL);
    svw_tile_kernel<<<EDGES/64, 256, 0, sB>>>(
        qpos, spos, esrc, edst, escal, Wr1, Wr2, br2, Pq_p, svw_p);
    cudaEventRecord(evJoin, sB);

    // main stream: bcomb, Wof1 (both layers), Wv (z=2), Wq0, Ff1-l0
    bcomb_kernel<<<3, 256>>>(Wf1, bo, bf1, bcomb_p);
    for (int l = 0; l < 2; l++)
        gemm64<<<dim3(MHID/64, CC/64, 1), thr>>>(
            Wo + (size_t)l*CC*CC, Wf1 + (size_t)l*CC*MHID, wof1_p + (size_t)l*CC*MHID,
            CC, MHID, CC, nullptr, nullptr, 0, 0LL, 0LL, 0LL);
    gemm128<<<dim3(1, SRCN/128, 2), thr>>>(
        sfeat, Wv, v_p, SRCN, CC, CC, nullptr, nullptr, 0,
        (long long)CC*CC, (long long)SRCN*CC);
    gemm64<<<dim3(CC/64, QN/64), thr>>>(
        qfeat, Wq, qproj_p, QN, CC, CC, nullptr, nullptr, 0, 0LL, 0LL, 0LL);
    gemm128<<<dim3(MHID/128, QN/128), thr>>>(
        qfeat, Wf1, Ff1_p, QN, MHID, CC, bcomb_p, nullptr, 0, 0LL, 0LL);

    // ---- join edge pipeline ----
    cudaStreamWaitEvent(0, evJoin, 0);

    // ================= layer 0 =================
    attn_kernel<<<QN/8, 256>>>(esrc, 0);
    cudaEventRecord(evAgg0, 0);
    // side: h0 = gelu(agg@Wof1_0 + Ff1)
    cudaStreamWaitEvent(sB, evAgg0, 0);
    gemm128<<<dim3(MHID/128, QN/128), thr, 0, sB>>>(
        agg_p, wof1_p, hbuf_p, QN, MHID, CC, nullptr, Ff1_p, 2, 0LL, 0LL);
    cudaEventRecord(evH0, sB);
    // main: out0 = agg@Wo0 + bo0 + qfeat
    gemm64<<<dim3(CC/64, QN/64), thr>>>(
        agg_p, Wo, obuf_p, QN, CC, CC, bo, qfeat, 0, 0LL, 0LL, 0LL);
    cudaStreamWaitEvent(0, evH0, 0);
    // main: feat = h0@Wf2_0 + bf2_0 + out0
    gemm64<<<dim3(CC/64, QN/64), thr>>>(
        hbuf_p, Wf2, feat_p, QN, CC, MHID, bf2, obuf_p, 0, 0LL, 0LL, 0LL);
    cudaEventRecord(evFeat, 0);

    // side: Ff1-l1 = feat@Wf1_1 + bcomb_1   (overlaps Wq-l1 + attn-l1)
    cudaStreamWaitEvent(sB, evFeat, 0);
    gemm128<<<dim3(MHID/128, QN/128), thr, 0, sB>>>(
        feat_p, Wf1 + (size_t)CC*MHID, Ff1_p, QN, MHID, CC,
        bcomb_p + MHID, nullptr, 0, 0LL, 0LL);

    // ================= layer 1 =================
    gemm64<<<dim3(CC/64, QN/64), thr>>>(
        feat_p, Wq + CC*CC, qproj_p, QN, CC, CC, nullptr, nullptr, 0, 0LL, 0LL, 0LL);
    attn_kernel<<<QN/8, 256>>>(esrc, 1);
    cudaEventRecord(evAgg1, 0);
    // side: h1 = gelu(agg@Wof1_1 + Ff1)   (Ff1-l1 ordered on same stream)
    cudaStreamWaitEvent(sB, evAgg1, 0);
    gemm128<<<dim3(MHID/128, QN/128), thr, 0, sB>>>(
        agg_p, wof1_p + (size_t)CC*MHID, hbuf_p, QN, MHID, CC, nullptr, Ff1_p, 2, 0LL, 0LL);
    cudaEventRecord(evH1, sB);
    // main: out1 = agg@Wo1 + bo1 + feat
    gemm64<<<dim3(CC/64, QN/64), thr>>>(
        agg_p, Wo + CC*CC, obuf_p, QN, CC, CC, bo + CC, feat_p, 0, 0LL, 0LL, 0LL);
    cudaStreamWaitEvent(0, evH1, 0);
    // main: d_out = h1@Wf2_1 + bf2_1 + out1
    gemm64<<<dim3(CC/64, QN/64), thr>>>(
        hbuf_p, Wf2 + (size_t)MHID*CC, (float*)d_out, QN, CC, MHID,
        bf2 + CC, obuf_p, 0, 0LL, 0LL, 0LL);
}

// round 16
// speedup vs baseline: 1.0248x; 1.0248x over previous
#include <cuda_runtime.h>
#include <math.h>

#define QN    4096
#define SRCN  32768
#define CC    128
#define KNN   32
#define EDGES (2*QN*KNN)   /* 262144 */
#define MHID  384

// ---------------- device scratch (static, allocation-free) ----------------
__device__ float g_v[2][SRCN*CC];       // src_feat @ Wv[l]
__device__ float g_Pq[2][QN*64];        // ctx @ Wr1[l][32:] + br1[l]
__device__ float g_svw[2][EDGES];
__device__ unsigned char g_mask[EDGES];
__device__ float g_obuf[QN*CC];
__device__ float g_hbuf[QN*MHID];
__device__ float g_feat[QN*CC];

// saturating tanh-gelu: t = 1 - 2/(exp(2y)+1) == tanh(y), inf-safe
__device__ __forceinline__ float gelu_fast(float x) {
    float u = 1.5957691216057308f * (x + 0.044715f*x*x*x);
    float e = __expf(u);
    float t = 1.0f - 2.0f/(e + 1.0f);
    return 0.5f*x*(1.0f + t);
}

// ============ big-tile SGEMM: 128x128 block, 8x8/thread, double-buffered ==
__global__ __launch_bounds__(256) void gemm128(
    const float* __restrict__ A, const float* __restrict__ B0, float* __restrict__ C0,
    int M, int N, int K,
    const float* __restrict__ bias, const float* __restrict__ resid, int act,
    long long strideB, long long strideC)
{
    const float* B = B0 + (long long)blockIdx.z * strideB;
    float*       C = C0 + (long long)blockIdx.z * strideC;
    __shared__ float As[2][8][128];
    __shared__ float Bs[2][8][128];
    int tid  = threadIdx.x;
    int m0   = blockIdx.y * 128, n0 = blockIdx.x * 128;
    int arow = tid >> 1,  acol = (tid & 1) * 4;
    int brow = tid >> 5,  bcol = (tid & 31) * 4;
    int tx   = tid & 15,  ty   = tid >> 4;
    float acc[8][8] = {};

    const float* Aptr = A + (size_t)(m0 + arow) * K + acol;
    const float* Bptr = B + (size_t)brow * N + n0 + bcol;

    float4 av = *(const float4*)Aptr;
    float4 bv = *(const float4*)Bptr;
    As[0][acol+0][arow] = av.x; As[0][acol+1][arow] = av.y;
    As[0][acol+2][arow] = av.z; As[0][acol+3][arow] = av.w;
    *(float4*)&Bs[0][brow][bcol] = bv;
    __syncthreads();

    int buf = 0;
    for (int kk = 8; kk < K; kk += 8) {
        av = *(const float4*)(Aptr + kk);
        bv = *(const float4*)(Bptr + (size_t)kk * N);
        #pragma unroll
        for (int k = 0; k < 8; k++) {
            float a[8], b[8];
            *(float4*)&a[0] = *(float4*)&As[buf][k][ty*4];
            *(float4*)&a[4] = *(float4*)&As[buf][k][64 + ty*4];
            *(float4*)&b[0] = *(float4*)&Bs[buf][k][tx*4];
            *(float4*)&b[4] = *(float4*)&Bs[buf][k][64 + tx*4];
            #pragma unroll
            for (int i = 0; i < 8; i++)
                #pragma unroll
                for (int j = 0; j < 8; j++)
                    acc[i][j] = fmaf(a[i], b[j], acc[i][j]);
        }
        buf ^= 1;
        As[buf][acol+0][arow] = av.x; As[buf][acol+1][arow] = av.y;
        As[buf][acol+2][arow] = av.z; As[buf][acol+3][arow] = av.w;
        *(float4*)&Bs[buf][brow][bcol] = bv;
        __syncthreads();
    }
    #pragma unroll
    for (int k = 0; k < 8; k++) {
        float a[8], b[8];
        *(float4*)&a[0] = *(float4*)&As[buf][k][ty*4];
        *(float4*)&a[4] = *(float4*)&As[buf][k][64 + ty*4];
        *(float4*)&b[0] = *(float4*)&Bs[buf][k][tx*4];
        *(float4*)&b[4] = *(float4*)&Bs[buf][k][64 + tx*4];
        #pragma unroll
        for (int i = 0; i < 8; i++)
            #pragma unroll
            for (int j = 0; j < 8; j++)
                acc[i][j] = fmaf(a[i], b[j], acc[i][j]);
    }

    #pragma unroll
    for (int i = 0; i < 8; i++) {
        int row = m0 + ((i < 4) ? (ty*4 + i) : (64 + ty*4 + i - 4));
        #pragma unroll
        for (int j = 0; j < 8; j++) {
            int col = n0 + ((j < 4) ? (tx*4 + j) : (64 + tx*4 + j - 4));
            float x = acc[i][j];
            if (bias)  x += bias[col];
            if (act)   x = gelu_fast(x);
            if (resid) x += resid[(size_t)row*N + col];
            C[(size_t)row*N + col] = x;
        }
    }
}

// ============ 64x64 SGEMM (z-batched) ====================================
__global__ __launch_bounds__(256) void gemm64(
    const float* __restrict__ A, const float* __restrict__ B0, float* __restrict__ C0,
    int M, int N, int K,
    const float* __restrict__ bias0, const float* __restrict__ resid, int act,
    long long strideB, long long strideC, long long strideBias)
{
    const float* B = B0 + (long long)blockIdx.z * strideB;
    float*       C = C0 + (long long)blockIdx.z * strideC;
    const float* bias = bias0 ? (bias0 + (long long)blockIdx.z * strideBias) : nullptr;
    __shared__ float As[16][64];
    __shared__ float Bs[16][64];
    int tid = threadIdx.x;
    int m0 = blockIdx.y * 64, n0 = blockIdx.x * 64;
    int arow = tid >> 2, acol = (tid & 3) * 4;
    int brow = tid >> 4, bcol = (tid & 15) * 4;
    int tx = tid & 15, ty = tid >> 4;
    float acc[4][4] = {};

    for (int kk = 0; kk < K; kk += 16) {
        float4 av = *(const float4*)&A[(size_t)(m0 + arow)*K + kk + acol];
        float4 bv = *(const float4*)&B[(size_t)(kk + brow)*N + n0 + bcol];
        As[acol+0][arow] = av.x; As[acol+1][arow] = av.y;
        As[acol+2][arow] = av.z; As[acol+3][arow] = av.w;
        *(float4*)&Bs[brow][bcol] = bv;
        __syncthreads();
        #pragma unroll
        for (int k = 0; k < 16; k++) {
            float4 a4 = *(float4*)&As[k][ty*4];
            float4 b4 = *(float4*)&Bs[k][tx*4];
            acc[0][0] = fmaf(a4.x, b4.x, acc[0][0]); acc[0][1] = fmaf(a4.x, b4.y, acc[0][1]);
            acc[0][2] = fmaf(a4.x, b4.z, acc[0][2]); acc[0][3] = fmaf(a4.x, b4.w, acc[0][3]);
            acc[1][0] = fmaf(a4.y, b4.x, acc[1][0]); acc[1][1] = fmaf(a4.y, b4.y, acc[1][1]);
            acc[1][2] = fmaf(a4.y, b4.z, acc[1][2]); acc[1][3] = fmaf(a4.y, b4.w, acc[1][3]);
            acc[2][0] = fmaf(a4.z, b4.x, acc[2][0]); acc[2][1] = fmaf(a4.z, b4.y, acc[2][1]);
            acc[2][2] = fmaf(a4.z, b4.z, acc[2][2]); acc[2][3] = fmaf(a4.z, b4.w, acc[2][3]);
            acc[3][0] = fmaf(a4.w, b4.x, acc[3][0]); acc[3][1] = fmaf(a4.w, b4.y, acc[3][1]);
            acc[3][2] = fmaf(a4.w, b4.z, acc[3][2]); acc[3][3] = fmaf(a4.w, b4.w, acc[3][3]);
        }
        __syncthreads();
    }
    #pragma unroll
    for (int i = 0; i < 4; i++) {
        int row = m0 + ty*4 + i;
        #pragma unroll
        for (int j = 0; j < 4; j++) {
            int col = n0 + tx*4 + j;
            float x = acc[i][j];
            if (bias)  x += bias[col];
            if (act)   x = gelu_fast(x);
            if (resid) x += resid[(size_t)row*N + col];
            C[(size_t)row*N + col] = x;
        }
    }
}

// ======== tiled svw: 64 edges/block (1 tile), both layers, smem GEMM =====
__global__ __launch_bounds__(256) void svw_tile_kernel(
    const float* __restrict__ qpos, const float* __restrict__ spos,
    const int* __restrict__ esrc, const int* __restrict__ edst,
    const int* __restrict__ escale,
    const float* __restrict__ Wr1, const float* __restrict__ Wr2,
    const float* __restrict__ br2,
    const float* __restrict__ Pq /* [2][QN*64] */,
    float* __restrict__ svw /* [2][EDGES] */)
{
    __shared__ float Ws[2][32][64];
    __shared__ float W2s[2][64][9];
    __shared__ float b2s[2][9];
    __shared__ float bess_s[64][33];
    __shared__ float sh_s[64][9];
    __shared__ float Pq_s[2][2][64];
    __shared__ float s1_s[64], c1_s[64], norm_s[64];
    __shared__ int   dst_s[2];
    __shared__ float red[16][66];

    int tid = threadIdx.x;
    int e0g = blockIdx.x * 64;

    for (int i = tid; i < 2*32*64; i += 256) {
        int l = i >> 11, rem = i & 2047;
        Ws[l][rem >> 6][rem & 63] = Wr1[l*96*64 + rem];
    }
    for (int i = tid; i < 2*64*9; i += 256) {
        int l = i / 576, rem = i % 576;
        W2s[l][rem / 9][rem % 9] = Wr2[l*64*9 + rem];
    }
    if (tid < 18) b2s[tid/9][tid%9] = br2[tid];

    if (tid < 64) {
        int eg = e0g + tid;
        int s = esrc[eg], d = edst[eg], sc = escale[eg];
        float cut = sc ? 0.2f : 0.1f;
        float dx = qpos[d*3+0] - spos[s*3+0];
        float dy = qpos[d*3+1] - spos[s*3+1];
        float dz = qpos[d*3+2] - spos[s*3+2];
        float d2 = __fadd_rn(__fadd_rn(__fmul_rn(dx,dx), __fmul_rn(dy,dy)), __fmul_rn(dz,dz));
        g_mask[eg] = (d2 < __fmul_rn(cut,cut)) ? 1 : 0;
        float r = sqrtf(d2 + 1e-12f), ir = 1.0f/r;
        float ux = dx*ir, uy = dy*ir, uz = dz*ir;
        sh_s[tid][0] = 1.0f;  sh_s[tid][1] = ux;  sh_s[tid][2] = uy;  sh_s[tid][3] = uz;
        sh_s[tid][4] = ux*uy; sh_s[tid][5] = uy*uz;
        sh_s[tid][6] = uz*uz - (1.0f/3.0f);
        sh_s[tid][7] = ux*uz; sh_s[tid][8] = ux*ux - uy*uy;
        float x = 3.14159265358979f * r / cut;
        float s1, c1; sincosf(x, &s1, &c1);
        s1_s[tid] = s1; c1_s[tid] = c1;
        norm_s[tid] = sqrtf(2.0f/cut) * ir;
        if (tid == 0)  dst_s[0] = d;
        if (tid == 32) dst_s[1] = d;
    }
    __syncthreads();

    {
        int l = tid >> 7, ql = (tid >> 6) & 1, h = tid & 63;
        Pq_s[l][ql][h] = Pq[(size_t)l*QN*64 + dst_s[ql]*64 + h];
    }
    {
        int e = tid & 63, kg = tid >> 6;
        float s1 = s1_s[e], c1 = c1_s[e], nrm = norm_s[e];
        float C = c1, S = s1;
        if (kg) {
            float c2 = c1*c1 - s1*s1, s2 = 2.0f*c1*s1;
            float c4 = c2*c2 - s2*s2, s4 = 2.0f*c2*s2;
            float c8 = c4*c4 - s4*s4, s8 = 2.0f*c4*s4;
            for (int q = 0; q < kg; q++) {
                float nc = C*c8 - S*s8, ns = S*c8 + C*s8;
                C = nc; S = ns;
            }
        }
        #pragma unroll
        for (int u = 0; u < 8; u++) {
            bess_s[e][kg*8 + u] = S * nrm;
            float nc = C*c1 - S*s1, ns = S*c1 + C*s1;
            C = nc; S = ns;
        }
    }
    __syncthreads();

    int te = tid & 15, th = tid >> 4;
    #pragma unroll
    for (int l = 0; l < 2; l++) {
        float acc[4][4];
        #pragma unroll
        for (int j = 0; j < 4; j++) {
            int e = te + 16*j, ql = e >> 5;
            #pragma unroll
            for (int hh = 0; hh < 4; hh++)
                acc[j][hh] = Pq_s[l][ql][th*4 + hh];
        }
        #pragma unroll 8
        for (int k = 0; k < 32; k++) {
            float4 w = *(const float4*)&Ws[l][k][th*4];
            #pragma unroll
            for (int j = 0; j < 4; j++) {
                float b = bess_s[te + 16*j][k];
                acc[j][0] = fmaf(b, w.x, acc[j][0]);
                acc[j][1] = fmaf(b, w.y, acc[j][1]);
                acc[j][2] = fmaf(b, w.z, acc[j][2]);
                acc[j][3] = fmaf(b, w.w, acc[j][3]);
            }
        }
        #pragma unroll
        for (int j = 0; j < 4; j++)
            #pragma unroll
            for (int hh = 0; hh < 4; hh++)
                acc[j][hh] = gelu_fast(acc[j][hh]);

        float w2r[4][9];
        #pragma unroll
        for (int hh = 0; hh < 4; hh++)
            #pragma unroll
            for (int i = 0; i < 9; i++)
                w2r[hh][i] = W2s[l][th*4 + hh][i];

        #pragma unroll
        for (int j = 0; j < 4; j++) {
            int e = te + 16*j;
            float shl[9];
            #pragma unroll
            for (int i = 0; i < 9; i++) shl[i] = sh_s[e][i];
            float p = 0.f;
            #pragma unroll
            for (int hh = 0; hh < 4; hh++) {
                float t2 = 0.f;
                #pragma unroll
                for (int i = 0; i < 9; i++) t2 = fmaf(w2r[hh][i], shl[i], t2);
                p = fmaf(acc[j][hh], t2, p);
            }
            red[th][e] = p;
        }
        __syncthreads();
        if (tid < 64) {
            float s = 0.f;
            #pragma unroll
            for (int u = 0; u < 16; u++) s += red[u][tid];
            float sb = 0.f;
            #pragma unroll
            for (int i = 0; i < 9; i++) sb = fmaf(b2s[l][i], sh_s[tid][i], sb);
            svw[(size_t)l*EDGES + e0g + tid] = s + sb;
        }
        __syncthreads();
    }
}

// ======== fused: qproj -> attention -> out-projection (+bias+resid) ======
// block = 8 queries (8 warps). Stages feat rows + agg rows in smem; the
// two mini-GEMMs (feat@Wq, agg@Wo) ride along with the attention gathers.
__global__ __launch_bounds__(256) void attn_fused(
    const int* __restrict__ esrc,
    const float* __restrict__ Wq, const float* __restrict__ Wo,
    const float* __restrict__ bo,
    const float* __restrict__ featin, float* __restrict__ outbuf, int layer)
{
    __shared__ float feat_s[8][132];
    __shared__ float agg_s[8][132];
    int tid  = threadIdx.x;
    int warp = tid >> 5, lane = tid & 31;
    int q0 = blockIdx.x * 8;

    // stage feat rows (8 x 128)
    {
        int r = tid >> 5, c4 = (tid & 31) * 4;
        *(float4*)&feat_s[r][c4] = *(const float4*)&featin[(size_t)(q0 + r)*CC + c4];
    }
    __syncthreads();

    // qproj: lane owns channels [4*lane, 4*lane+4)
    int q = q0 + warp;
    float4 qv = make_float4(0.f, 0.f, 0.f, 0.f);
    #pragma unroll 8
    for (int k = 0; k < CC; k++) {
        float f = feat_s[warp][k];
        float4 w = *(const float4*)&Wq[(size_t)k*CC + lane*4];
        qv.x = fmaf(f, w.x, qv.x); qv.y = fmaf(f, w.y, qv.y);
        qv.z = fmaf(f, w.z, qv.z); qv.w = fmaf(f, w.w, qv.w);
    }

    const float* vbuf = g_v[layer];
    const float* svw  = g_svw[layer];

    float m[4], d[4], acc[4][4];
    #pragma unroll
    for (int u = 0; u < 4; u++) {
        m[u] = -1e30f; d[u] = 0.f;
        acc[u][0]=acc[u][1]=acc[u][2]=acc[u][3]=0.f;
    }

    #pragma unroll
    for (int half = 0; half < 2; half++) {
        int base = q*KNN + half*QN*KNN;
        #pragma unroll
        for (int jj = 0; jj < 8; jj++) {
            #pragma unroll
            for (int u = 0; u < 4; u++) {
                int e = base + jj*4 + u;
                int src = esrc[e];
                float w  = svw[e];
                float mf = (float)g_mask[e];
                float4 v4 = *(const float4*)&vbuf[(size_t)src*CC + lane*4];
                float p = qv.x*v4.x + qv.y*v4.y + qv.z*v4.z + qv.w*v4.w;
                p += __shfl_xor_sync(0xffffffffu, p, 1);
                p += __shfl_xor_sync(0xffffffffu, p, 2);
                p += __shfl_xor_sync(0xffffffffu, p, 4);
                float z = p * w * 0.17677669529663687f;
                float lk = (z > 0.f) ? z : 0.2f*z;
                float logit = (mf > 0.f) ? lk : -1e30f;
                if (logit > m[u]) {
                    float scl = __expf(m[u] - logit);
                    d[u]      *= scl;
                    acc[u][0] *= scl; acc[u][1] *= scl;
                    acc[u][2] *= scl; acc[u][3] *= scl;
                    m[u] = logit;
                }
                float el = __expf(logit - m[u]) * mf;
                d[u] += el;
                float ew = el * w;
                acc[u][0] = fmaf(ew, v4.x, acc[u][0]);
                acc[u][1] = fmaf(ew, v4.y, acc[u][1]);
                acc[u][2] = fmaf(ew, v4.z, acc[u][2]);
                acc[u][3] = fmaf(ew, v4.w, acc[u][3]);
            }
        }
    }
    float M = fmaxf(fmaxf(m[0], m[1]), fmaxf(m[2], m[3]));
    float D = 0.f, A0 = 0.f, A1 = 0.f, A2 = 0.f, A3 = 0.f;
    #pragma unroll
    for (int u = 0; u < 4; u++) {
        float s = __expf(m[u] - M);
        D  += d[u]*s;
        A0 = fmaf(acc[u][0], s, A0);
        A1 = fmaf(acc[u][1], s, A1);
        A2 = fmaf(acc[u][2], s, A2);
        A3 = fmaf(acc[u][3], s, A3);
    }
    float inv = 1.0f / (D + 1e-12f);
    agg_s[warp][lane*4+0] = A0*inv;
    agg_s[warp][lane*4+1] = A1*inv;
    agg_s[warp][lane*4+2] = A2*inv;
    agg_s[warp][lane*4+3] = A3*inv;
    __syncthreads();

    // out = agg @ Wo + bo + feat
    {
        int r = tid >> 5, c4 = (tid & 31) * 4;
        float4 o = *(const float4*)&bo[c4];
        #pragma unroll 8
        for (int k = 0; k < CC; k++) {
            float a = agg_s[r][k];
            float4 w = *(const float4*)&Wo[(size_t)k*CC + c4];
            o.x = fmaf(a, w.x, o.x); o.y = fmaf(a, w.y, o.y);
            o.z = fmaf(a, w.z, o.z); o.w = fmaf(a, w.w, o.w);
        }
        o.x += feat_s[r][c4+0]; o.y += feat_s[r][c4+1];
        o.z += feat_s[r][c4+2]; o.w += feat_s[r][c4+3];
        *(float4*)&outbuf[(size_t)(q0 + r)*CC + c4] = o;
    }
}

// ---------------- host orchestration -------------------------------------
// Fork-join prework; per-layer chain: attn_fused -> Wf1 -> Wf2 (3 kernels).
extern "C" void kernel_launch(void* const* d_in, const int* in_sizes, int n_in,
                              void* d_out, int out_size)
{
    const float* qpos  = (const float*)d_in[0];
    const float* qfeat = (const float*)d_in[1];
    const float* spos  = (const float*)d_in[2];
    const float* sfeat = (const float*)d_in[3];
    const float* ctx   = (const float*)d_in[4];
    const float* Wq    = (const float*)d_in[5];
    const float* Wv    = (const float*)d_in[6];
    const float* Wo    = (const float*)d_in[7];
    const float* bo    = (const float*)d_in[8];
    const float* Wr1   = (const float*)d_in[9];
    const float* br1   = (const float*)d_in[10];
    const float* Wr2   = (const float*)d_in[11];
    const float* br2   = (const float*)d_in[12];
    const float* Wf1   = (const float*)d_in[13];
    const float* bf1   = (const float*)d_in[14];
    const float* Wf2   = (const float*)d_in[15];
    const float* bf2   = (const float*)d_in[16];
    const int*   esrc  = (const int*)d_in[17];
    const int*   edst  = (const int*)d_in[18];
    const int*   escal = (const int*)d_in[19];
    (void)in_sizes; (void)n_in; (void)out_size;

    float *v_p, *Pq_p, *obuf_p, *hbuf_p, *feat_p, *svw_p;
    cudaGetSymbolAddress((void**)&v_p,     g_v);
    cudaGetSymbolAddress((void**)&Pq_p,    g_Pq);
    cudaGetSymbolAddress((void**)&obuf_p,  g_obuf);
    cudaGetSymbolAddress((void**)&hbuf_p,  g_hbuf);
    cudaGetSymbolAddress((void**)&feat_p,  g_feat);
    cudaGetSymbolAddress((void**)&svw_p,   g_svw);

    static cudaStream_t sB = nullptr;
    static cudaEvent_t  evFork = nullptr, evJoin = nullptr;
    if (sB == nullptr) {
        cudaStreamCreateWithFlags(&sB, cudaStreamNonBlocking);
        cudaEventCreateWithFlags(&evFork, cudaEventDisableTiming);
        cudaEventCreateWithFlags(&evJoin, cudaEventDisableTiming);
    }

    dim3 thr(256);

    // ---- fork ----
    cudaEventRecord(evFork, 0);
    cudaStreamWaitEvent(sB, evFork, 0);

    // side stream: Pq (z=2) -> svw
    gemm64<<<dim3(1, QN/64, 2), thr, 0, sB>>>(
        ctx, Wr1 + 32*64, Pq_p, QN, 64, 64, br1, nullptr, 0,
        96LL*64, (long long)QN*64, 64LL);
    svw_tile_kernel<<<EDGES/64, 256, 0, sB>>>(
        qpos, spos, esrc, edst, escal, Wr1, Wr2, br2, Pq_p, svw_p);
    cudaEventRecord(evJoin, sB);

    // main stream: Wv (z=2)
    gemm128<<<dim3(1, SRCN/128, 2), thr>>>(
        sfeat, Wv, v_p, SRCN, CC, CC, nullptr, nullptr, 0,
        (long long)CC*CC, (long long)SRCN*CC);

    // ---- join ----
    cudaStreamWaitEvent(0, evJoin, 0);

    const float* featin = qfeat;
    for (int l = 0; l < 2; l++) {
        // fused qproj + attention + out-projection (+bias+residual)
        attn_fused<<<QN/8, 256>>>(esrc, Wq + (size_t)l*CC*CC,
                                  Wo + (size_t)l*CC*CC, bo + l*CC,
                                  featin, obuf_p, l);
        // h = gelu(out @ Wf1 + bf1)
        gemm128<<<dim3(MHID/128, QN/128, 1), thr>>>(
            obuf_p, Wf1 + (size_t)l*CC*MHID, hbuf_p, QN, MHID, CC,
            bf1 + l*MHID, nullptr, 1, 0LL, 0LL);
        // feat_next = h @ Wf2 + bf2 + out
        float* outp = (l == 0) ? feat_p : (float*)d_out;
        gemm64<<<dim3(CC/64, QN/64), thr>>>(
            hbuf_p, Wf2 + (size_t)l*MHID*CC, outp, QN, CC, MHID,
            bf2 + l*CC, obuf_p, 0, 0LL, 0LL, 0LL);
        featin = feat_p;
    }
}

// round 17
// speedup vs baseline: 1.1672x; 1.1389x over previous
#include <cuda_runtime.h>
#include <math.h>

#define QN    4096
#define SRCN  32768
#define CC    128
#define KNN   32
#define EDGES (2*QN*KNN)   /* 262144 */
#define MHID  384

// ---------------- device scratch (static, allocation-free) ----------------
__device__ float g_v[2][SRCN*CC];       // src_feat @ Wv[l]
__device__ float g_qproj[QN*CC];
__device__ float g_Pq[2][QN*64];        // ctx @ Wr1[l][32:] + br1[l]
__device__ float g_svw[2][EDGES];
__device__ unsigned char g_mask[EDGES];
__device__ float g_agg[QN*CC];
__device__ float g_obuf[QN*CC];
__device__ float g_hbuf[QN*MHID];
__device__ float g_feat[QN*CC];
__device__ float g_part[3][QN*CC];      // split-K partials for Wf2

// saturating tanh-gelu: t = 1 - 2/(exp(2y)+1) == tanh(y), inf-safe
__device__ __forceinline__ float gelu_fast(float x) {
    float u = 1.5957691216057308f * (x + 0.044715f*x*x*x);
    float e = __expf(u);
    float t = 1.0f - 2.0f/(e + 1.0f);
    return 0.5f*x*(1.0f + t);
}

// ============ big-tile SGEMM: 128x128 block, 8x8/thread, double-buffered ==
__global__ __launch_bounds__(256) void gemm128(
    const float* __restrict__ A, const float* __restrict__ B0, float* __restrict__ C0,
    int M, int N, int K,
    const float* __restrict__ bias, const float* __restrict__ resid, int act,
    long long strideB, long long strideC)
{
    const float* B = B0 + (long long)blockIdx.z * strideB;
    float*       C = C0 + (long long)blockIdx.z * strideC;
    __shared__ float As[2][8][128];
    __shared__ float Bs[2][8][128];
    int tid  = threadIdx.x;
    int m0   = blockIdx.y * 128, n0 = blockIdx.x * 128;
    int arow = tid >> 1,  acol = (tid & 1) * 4;
    int brow = tid >> 5,  bcol = (tid & 31) * 4;
    int tx   = tid & 15,  ty   = tid >> 4;
    float acc[8][8] = {};

    const float* Aptr = A + (size_t)(m0 + arow) * K + acol;
    const float* Bptr = B + (size_t)brow * N + n0 + bcol;

    float4 av = *(const float4*)Aptr;
    float4 bv = *(const float4*)Bptr;
    As[0][acol+0][arow] = av.x; As[0][acol+1][arow] = av.y;
    As[0][acol+2][arow] = av.z; As[0][acol+3][arow] = av.w;
    *(float4*)&Bs[0][brow][bcol] = bv;
    __syncthreads();

    int buf = 0;
    for (int kk = 8; kk < K; kk += 8) {
        av = *(const float4*)(Aptr + kk);
        bv = *(const float4*)(Bptr + (size_t)kk * N);
        #pragma unroll
        for (int k = 0; k < 8; k++) {
            float a[8], b[8];
            *(float4*)&a[0] = *(float4*)&As[buf][k][ty*4];
            *(float4*)&a[4] = *(float4*)&As[buf][k][64 + ty*4];
            *(float4*)&b[0] = *(float4*)&Bs[buf][k][tx*4];
            *(float4*)&b[4] = *(float4*)&Bs[buf][k][64 + tx*4];
            #pragma unroll
            for (int i = 0; i < 8; i++)
                #pragma unroll
                for (int j = 0; j < 8; j++)
                    acc[i][j] = fmaf(a[i], b[j], acc[i][j]);
        }
        buf ^= 1;
        As[buf][acol+0][arow] = av.x; As[buf][acol+1][arow] = av.y;
        As[buf][acol+2][arow] = av.z; As[buf][acol+3][arow] = av.w;
        *(float4*)&Bs[buf][brow][bcol] = bv;
        __syncthreads();
    }
    #pragma unroll
    for (int k = 0; k < 8; k++) {
        float a[8], b[8];
        *(float4*)&a[0] = *(float4*)&As[buf][k][ty*4];
        *(float4*)&a[4] = *(float4*)&As[buf][k][64 + ty*4];
        *(float4*)&b[0] = *(float4*)&Bs[buf][k][tx*4];
        *(float4*)&b[4] = *(float4*)&Bs[buf][k][64 + tx*4];
        #pragma unroll
        for (int i = 0; i < 8; i++)
            #pragma unroll
            for (int j = 0; j < 8; j++)
                acc[i][j] = fmaf(a[i], b[j], acc[i][j]);
    }

    #pragma unroll
    for (int i = 0; i < 8; i++) {
        int row = m0 + ((i < 4) ? (ty*4 + i) : (64 + ty*4 + i - 4));
        #pragma unroll
        for (int j = 0; j < 8; j++) {
            int col = n0 + ((j < 4) ? (tx*4 + j) : (64 + tx*4 + j - 4));
            float x = acc[i][j];
            if (bias)  x += bias[col];
            if (act)   x = gelu_fast(x);
            if (resid) x += resid[(size_t)row*N + col];
            C[(size_t)row*N + col] = x;
        }
    }
}

// ============ 64x64 SGEMM (z-batched, separate lda + A-stride) ===========
__global__ __launch_bounds__(256) void gemm64(
    const float* __restrict__ A0, const float* __restrict__ B0, float* __restrict__ C0,
    int M, int N, int K, int lda,
    const float* __restrict__ bias0, const float* __restrict__ resid, int act,
    long long strideA, long long strideB, long long strideC, long long strideBias)
{
    const float* A = A0 + (long long)blockIdx.z * strideA;
    const float* B = B0 + (long long)blockIdx.z * strideB;
    float*       C = C0 + (long long)blockIdx.z * strideC;
    const float* bias = bias0 ? (bias0 + (long long)blockIdx.z * strideBias) : nullptr;
    __shared__ float As[16][64];
    __shared__ float Bs[16][64];
    int tid = threadIdx.x;
    int m0 = blockIdx.y * 64, n0 = blockIdx.x * 64;
    int arow = tid >> 2, acol = (tid & 3) * 4;
    int brow = tid >> 4, bcol = (tid & 15) * 4;
    int tx = tid & 15, ty = tid >> 4;
    float acc[4][4] = {};

    for (int kk = 0; kk < K; kk += 16) {
        float4 av = *(const float4*)&A[(size_t)(m0 + arow)*lda + kk + acol];
        float4 bv = *(const float4*)&B[(size_t)(kk + brow)*N + n0 + bcol];
        As[acol+0][arow] = av.x; As[acol+1][arow] = av.y;
        As[acol+2][arow] = av.z; As[acol+3][arow] = av.w;
        *(float4*)&Bs[brow][bcol] = bv;
        __syncthreads();
        #pragma unroll
        for (int k = 0; k < 16; k++) {
            float4 a4 = *(float4*)&As[k][ty*4];
            float4 b4 = *(float4*)&Bs[k][tx*4];
            acc[0][0] = fmaf(a4.x, b4.x, acc[0][0]); acc[0][1] = fmaf(a4.x, b4.y, acc[0][1]);
            acc[0][2] = fmaf(a4.x, b4.z, acc[0][2]); acc[0][3] = fmaf(a4.x, b4.w, acc[0][3]);
            acc[1][0] = fmaf(a4.y, b4.x, acc[1][0]); acc[1][1] = fmaf(a4.y, b4.y, acc[1][1]);
            acc[1][2] = fmaf(a4.y, b4.z, acc[1][2]); acc[1][3] = fmaf(a4.y, b4.w, acc[1][3]);
            acc[2][0] = fmaf(a4.z, b4.x, acc[2][0]); acc[2][1] = fmaf(a4.z, b4.y, acc[2][1]);
            acc[2][2] = fmaf(a4.z, b4.z, acc[2][2]); acc[2][3] = fmaf(a4.z, b4.w, acc[2][3]);
            acc[3][0] = fmaf(a4.w, b4.x, acc[3][0]); acc[3][1] = fmaf(a4.w, b4.y, acc[3][1]);
            acc[3][2] = fmaf(a4.w, b4.z, acc[3][2]); acc[3][3] = fmaf(a4.w, b4.w, acc[3][3]);
        }
        __syncthreads();
    }
    #pragma unroll
    for (int i = 0; i < 4; i++) {
        int row = m0 + ty*4 + i;
        #pragma unroll
        for (int j = 0; j < 4; j++) {
            int col = n0 + tx*4 + j;
            float x = acc[i][j];
            if (bias)  x += bias[col];
            if (act)   x = gelu_fast(x);
            if (resid) x += resid[(size_t)row*N + col];
            C[(size_t)row*N + col] = x;
        }
    }
}

// ---- reduce 3 split-K partials + bias + resid -> out (float4) -----------
__global__ __launch_bounds__(256) void reduce3_kernel(
    const float* __restrict__ part, const float* __restrict__ bias,
    const float* __restrict__ resid, float* __restrict__ out)
{
    int i = blockIdx.x*blockDim.x + threadIdx.x;       // float4 index
    const int TOT4 = QN*CC/4;
    if (i >= TOT4) return;
    int col4 = (i & (CC/4 - 1)) * 4;
    float4 a = *(const float4*)&part[(size_t)i*4];
    float4 b = *(const float4*)&part[(size_t)QN*CC + (size_t)i*4];
    float4 c = *(const float4*)&part[(size_t)2*QN*CC + (size_t)i*4];
    float4 r = *(const float4*)&resid[(size_t)i*4];
    float4 o;
    o.x = a.x + b.x + c.x + bias[col4+0] + r.x;
    o.y = a.y + b.y + c.y + bias[col4+1] + r.y;
    o.z = a.z + b.z + c.z + bias[col4+2] + r.z;
    o.w = a.w + b.w + c.w + bias[col4+3] + r.w;
    *(float4*)&out[(size_t)i*4] = o;
}

// ======== tiled svw: 64 edges/block (1 tile), both layers, smem GEMM =====
__global__ __launch_bounds__(256) void svw_tile_kernel(
    const float* __restrict__ qpos, const float* __restrict__ spos,
    const int* __restrict__ esrc, const int* __restrict__ edst,
    const int* __restrict__ escale,
    const float* __restrict__ Wr1, const float* __restrict__ Wr2,
    const float* __restrict__ br2,
    const float* __restrict__ Pq /* [2][QN*64] */,
    float* __restrict__ svw /* [2][EDGES] */)
{
    __shared__ float Ws[2][32][64];
    __shared__ float W2s[2][64][9];
    __shared__ float b2s[2][9];
    __shared__ float bess_s[64][33];
    __shared__ float sh_s[64][9];
    __shared__ float Pq_s[2][2][64];
    __shared__ float s1_s[64], c1_s[64], norm_s[64];
    __shared__ int   dst_s[2];
    __shared__ float red[16][66];

    int tid = threadIdx.x;
    int e0g = blockIdx.x * 64;

    for (int i = tid; i < 2*32*64; i += 256) {
        int l = i >> 11, rem = i & 2047;
        Ws[l][rem >> 6][rem & 63] = Wr1[l*96*64 + rem];
    }
    for (int i = tid; i < 2*64*9; i += 256) {
        int l = i / 576, rem = i % 576;
        W2s[l][rem / 9][rem % 9] = Wr2[l*64*9 + rem];
    }
    if (tid < 18) b2s[tid/9][tid%9] = br2[tid];

    if (tid < 64) {
        int eg = e0g + tid;
        int s = esrc[eg], d = edst[eg], sc = escale[eg];
        float cut = sc ? 0.2f : 0.1f;
        float dx = qpos[d*3+0] - spos[s*3+0];
        float dy = qpos[d*3+1] - spos[s*3+1];
        float dz = qpos[d*3+2] - spos[s*3+2];
        float d2 = __fadd_rn(__fadd_rn(__fmul_rn(dx,dx), __fmul_rn(dy,dy)), __fmul_rn(dz,dz));
        g_mask[eg] = (d2 < __fmul_rn(cut,cut)) ? 1 : 0;
        float r = sqrtf(d2 + 1e-12f), ir = 1.0f/r;
        float ux = dx*ir, uy = dy*ir, uz = dz*ir;
        sh_s[tid][0] = 1.0f;  sh_s[tid][1] = ux;  sh_s[tid][2] = uy;  sh_s[tid][3] = uz;
        sh_s[tid][4] = ux*uy; sh_s[tid][5] = uy*uz;
        sh_s[tid][6] = uz*uz - (1.0f/3.0f);
        sh_s[tid][7] = ux*uz; sh_s[tid][8] = ux*ux - uy*uy;
        float x = 3.14159265358979f * r / cut;
        float s1, c1; sincosf(x, &s1, &c1);
        s1_s[tid] = s1; c1_s[tid] = c1;
        norm_s[tid] = sqrtf(2.0f/cut) * ir;
        if (tid == 0)  dst_s[0] = d;
        if (tid == 32) dst_s[1] = d;
    }
    __syncthreads();

    {
        int l = tid >> 7, ql = (tid >> 6) & 1, h = tid & 63;
        Pq_s[l][ql][h] = Pq[(size_t)l*QN*64 + dst_s[ql]*64 + h];
    }
    {
        int e = tid & 63, kg = tid >> 6;
        float s1 = s1_s[e], c1 = c1_s[e], nrm = norm_s[e];
        float C = c1, S = s1;
        if (kg) {
            float c2 = c1*c1 - s1*s1, s2 = 2.0f*c1*s1;
            float c4 = c2*c2 - s2*s2, s4 = 2.0f*c2*s2;
            float c8 = c4*c4 - s4*s4, s8 = 2.0f*c4*s4;
            for (int q = 0; q < kg; q++) {
                float nc = C*c8 - S*s8, ns = S*c8 + C*s8;
                C = nc; S = ns;
            }
        }
        #pragma unroll
        for (int u = 0; u < 8; u++) {
            bess_s[e][kg*8 + u] = S * nrm;
            float nc = C*c1 - S*s1, ns = S*c1 + C*s1;
            C = nc; S = ns;
        }
    }
    __syncthreads();

    int te = tid & 15, th = tid >> 4;
    #pragma unroll
    for (int l = 0; l < 2; l++) {
        float acc[4][4];
        #pragma unroll
        for (int j = 0; j < 4; j++) {
            int e = te + 16*j, ql = e >> 5;
            #pragma unroll
            for (int hh = 0; hh < 4; hh++)
                acc[j][hh] = Pq_s[l][ql][th*4 + hh];
        }
        #pragma unroll 8
        for (int k = 0; k < 32; k++) {
            float4 w = *(const float4*)&Ws[l][k][th*4];
            #pragma unroll
            for (int j = 0; j < 4; j++) {
                float b = bess_s[te + 16*j][k];
                acc[j][0] = fmaf(b, w.x, acc[j][0]);
                acc[j][1] = fmaf(b, w.y, acc[j][1]);
                acc[j][2] = fmaf(b, w.z, acc[j][2]);
                acc[j][3] = fmaf(b, w.w, acc[j][3]);
            }
        }
        #pragma unroll
        for (int j = 0; j < 4; j++)
            #pragma unroll
            for (int hh = 0; hh < 4; hh++)
                acc[j][hh] = gelu_fast(acc[j][hh]);

        float w2r[4][9];
        #pragma unroll
        for (int hh = 0; hh < 4; hh++)
            #pragma unroll
            for (int i = 0; i < 9; i++)
                w2r[hh][i] = W2s[l][th*4 + hh][i];

        #pragma unroll
        for (int j = 0; j < 4; j++) {
            int e = te + 16*j;
            float shl[9];
            #pragma unroll
            for (int i = 0; i < 9; i++) shl[i] = sh_s[e][i];
            float p = 0.f;
            #pragma unroll
            for (int hh = 0; hh < 4; hh++) {
                float t2 = 0.f;
                #pragma unroll
                for (int i = 0; i < 9; i++) t2 = fmaf(w2r[hh][i], shl[i], t2);
                p = fmaf(acc[j][hh], t2, p);
            }
            red[th][e] = p;
        }
        __syncthreads();
        if (tid < 64) {
            float s = 0.f;
            #pragma unroll
            for (int u = 0; u < 16; u++) s += red[u][tid];
            float sb = 0.f;
            #pragma unroll
            for (int i = 0; i < 9; i++) sb = fmaf(b2s[l][i], sh_s[tid][i], sb);
            svw[(size_t)l*EDGES + e0g + tid] = s + sb;
        }
        __syncthreads();
    }
}

// ---------------- per-query attention: skip-rescale online softmax -------
__global__ __launch_bounds__(256) void attn_kernel(const int* __restrict__ esrc, int layer)
{
    int lane = threadIdx.x & 31;
    int q = (blockIdx.x * blockDim.x + threadIdx.x) >> 5;
    if (q >= QN) return;
    const float* vbuf = g_v[layer];
    const float* svw  = g_svw[layer];

    float4 qv = *(const float4*)&g_qproj[q*CC + lane*4];
    float m[4], d[4], acc[4][4];
    #pragma unroll
    for (int u = 0; u < 4; u++) {
        m[u] = -1e30f; d[u] = 0.f;
        acc[u][0]=acc[u][1]=acc[u][2]=acc[u][3]=0.f;
    }

    #pragma unroll
    for (int half = 0; half < 2; half++) {
        int base = q*KNN + half*QN*KNN;
        #pragma unroll
        for (int jj = 0; jj < 8; jj++) {
            #pragma unroll
            for (int u = 0; u < 4; u++) {
                int e = base + jj*4 + u;
                int src = esrc[e];
                float w  = svw[e];
                float mf = (float)g_mask[e];
                float4 v4 = *(const float4*)&vbuf[(size_t)src*CC + lane*4];
                float p = qv.x*v4.x + qv.y*v4.y + qv.z*v4.z + qv.w*v4.w;
                p += __shfl_xor_sync(0xffffffffu, p, 1);
                p += __shfl_xor_sync(0xffffffffu, p, 2);
                p += __shfl_xor_sync(0xffffffffu, p, 4);
                float z = p * w * 0.17677669529663687f;
                float lk = (z > 0.f) ? z : 0.2f*z;
                float logit = (mf > 0.f) ? lk : -1e30f;
                if (logit > m[u]) {
                    float scl = __expf(m[u] - logit);
                    d[u]      *= scl;
                    acc[u][0] *= scl; acc[u][1] *= scl;
                    acc[u][2] *= scl; acc[u][3] *= scl;
                    m[u] = logit;
                }
                float el = __expf(logit - m[u]) * mf;
                d[u] += el;
                float ew = el * w;
                acc[u][0] = fmaf(ew, v4.x, acc[u][0]);
                acc[u][1] = fmaf(ew, v4.y, acc[u][1]);
                acc[u][2] = fmaf(ew, v4.z, acc[u][2]);
                acc[u][3] = fmaf(ew, v4.w, acc[u][3]);
            }
        }
    }
    float M = fmaxf(fmaxf(m[0], m[1]), fmaxf(m[2], m[3]));
    float D = 0.f, A0 = 0.f, A1 = 0.f, A2 = 0.f, A3 = 0.f;
    #pragma unroll
    for (int u = 0; u < 4; u++) {
        float s = __expf(m[u] - M);
        D  += d[u]*s;
        A0 = fmaf(acc[u][0], s, A0);
        A1 = fmaf(acc[u][1], s, A1);
        A2 = fmaf(acc[u][2], s, A2);
        A3 = fmaf(acc[u][3], s, A3);
    }
    float inv = 1.0f / (D + 1e-12f);
    *(float4*)&g_agg[q*CC + lane*4] = make_float4(A0*inv, A1*inv, A2*inv, A3*inv);
}

// ---------------- host orchestration -------------------------------------
// R11 structure + split-K3 Wf2 (partials + reduce).
extern "C" void kernel_launch(void* const* d_in, const int* in_sizes, int n_in,
                              void* d_out, int out_size)
{
    const float* qpos  = (const float*)d_in[0];
    const float* qfeat = (const float*)d_in[1];
    const float* spos  = (const float*)d_in[2];
    const float* sfeat = (const float*)d_in[3];
    const float* ctx   = (const float*)d_in[4];
    const float* Wq    = (const float*)d_in[5];
    const float* Wv    = (const float*)d_in[6];
    const float* Wo    = (const float*)d_in[7];
    const float* bo    = (const float*)d_in[8];
    const float* Wr1   = (const float*)d_in[9];
    const float* br1   = (const float*)d_in[10];
    const float* Wr2   = (const float*)d_in[11];
    const float* br2   = (const float*)d_in[12];
    const float* Wf1   = (const float*)d_in[13];
    const float* bf1   = (const float*)d_in[14];
    const float* Wf2   = (const float*)d_in[15];
    const float* bf2   = (const float*)d_in[16];
    const int*   esrc  = (const int*)d_in[17];
    const int*   edst  = (const int*)d_in[18];
    const int*   escal = (const int*)d_in[19];
    (void)in_sizes; (void)n_in; (void)out_size;

    float *v_p, *qproj_p, *Pq_p, *agg_p, *obuf_p, *hbuf_p, *feat_p, *svw_p, *part_p;
    cudaGetSymbolAddress((void**)&v_p,     g_v);
    cudaGetSymbolAddress((void**)&qproj_p, g_qproj);
    cudaGetSymbolAddress((void**)&Pq_p,    g_Pq);
    cudaGetSymbolAddress((void**)&agg_p,   g_agg);
    cudaGetSymbolAddress((void**)&obuf_p,  g_obuf);
    cudaGetSymbolAddress((void**)&hbuf_p,  g_hbuf);
    cudaGetSymbolAddress((void**)&feat_p,  g_feat);
    cudaGetSymbolAddress((void**)&svw_p,   g_svw);
    cudaGetSymbolAddress((void**)&part_p,  g_part);

    static cudaStream_t sB = nullptr;
    static cudaEvent_t  evFork = nullptr, evJoin = nullptr;
    if (sB == nullptr) {
        cudaStreamCreateWithFlags(&sB, cudaStreamNonBlocking);
        cudaEventCreateWithFlags(&evFork, cudaEventDisableTiming);
        cudaEventCreateWithFlags(&evJoin, cudaEventDisableTiming);
    }

    dim3 thr(256);

    // ---- fork ----
    cudaEventRecord(evFork, 0);
    cudaStreamWaitEvent(sB, evFork, 0);

    // side stream: Pq (z=2) -> svw
    gemm64<<<dim3(1, QN/64, 2), thr, 0, sB>>>(
        ctx, Wr1 + 32*64, Pq_p, QN, 64, 64, 64, br1, nullptr, 0,
        0LL, 96LL*64, (long long)QN*64, 64LL);
    svw_tile_kernel<<<EDGES/64, 256, 0, sB>>>(
        qpos, spos, esrc, edst, escal, Wr1, Wr2, br2, Pq_p, svw_p);
    cudaEventRecord(evJoin, sB);

    // main stream: Wv (z=2) + qproj(l0)
    gemm128<<<dim3(1, SRCN/128, 2), thr>>>(
        sfeat, Wv, v_p, SRCN, CC, CC, nullptr, nullptr, 0,
        (long long)CC*CC, (long long)SRCN*CC);
    gemm64<<<dim3(CC/64, QN/64), thr>>>(
        qfeat, Wq, qproj_p, QN, CC, CC, CC, nullptr, nullptr, 0, 0LL, 0LL, 0LL, 0LL);

    // ---- join ----
    cudaStreamWaitEvent(0, evJoin, 0);

    const float* featin = qfeat;
    for (int l = 0; l < 2; l++) {
        if (l == 1)
            gemm64<<<dim3(CC/64, QN/64), thr>>>(
                featin, Wq + l*CC*CC, qproj_p, QN, CC, CC, CC,
                nullptr, nullptr, 0, 0LL, 0LL, 0LL, 0LL);
        attn_kernel<<<QN/8, 256>>>(esrc, l);
        gemm64<<<dim3(CC/64, QN/64), thr>>>(
            agg_p, Wo + l*CC*CC, obuf_p, QN, CC, CC, CC,
            bo + l*CC, featin, 0, 0LL, 0LL, 0LL, 0LL);
        gemm128<<<dim3(MHID/128, QN/128, 1), thr>>>(
            obuf_p, Wf1 + l*CC*MHID, hbuf_p, QN, MHID, CC, bf1 + l*MHID, nullptr, 1,
            0LL, 0LL);
        // Wf2 split-K3: partials over z (K-chunks of 128), lda = MHID
        gemm64<<<dim3(CC/64, QN/64, 3), thr>>>(
            hbuf_p, Wf2 + (size_t)l*MHID*CC, part_p, QN, CC, 128, MHID,
            nullptr, nullptr, 0,
            128LL, 128LL*CC, (long long)QN*CC, 0LL);
        float* outp = (l == 0) ? feat_p : (float*)d_out;
        reduce3_kernel<<<(QN*CC/4 + 255)/256, thr>>>(
            part_p, bf2 + l*CC, obuf_p, outp);
        featin = feat_p;
    }
}